// round 3
// baseline (speedup 1.0000x reference)
#include <cuda_runtime.h>
#include <math.h>

#define H    1024
#define NH   16
#define HD   64
#define FF   4096
#define SEQ  2048
#define BTOK 8192   // 4 * 2048 tokens

// ---------------------------------------------------------------------------
// Scratch (static __device__ globals: allocation-free rule)
// ---------------------------------------------------------------------------
__device__ float g_q[BTOK * H];
__device__ float g_k[BTOK * H];
__device__ float g_v[BTOK * H];
__device__ float g_ctx[BTOK * H];
__device__ float g_x[BTOK * H];
__device__ float g_inter[(size_t)BTOK * FF];
__device__ float g_ffn[BTOK * H];

// ---------------------------------------------------------------------------
// Generic SGEMM: C[M,N] = A[M,K] @ B[K,N] + bias, optional exact-gelu+clamp.
// 128x128 block tile, BK=8, 256 threads, 8x8 register micro-tile.
// Assumes M%128==0, N%128==0, K%8==0 (true for all shapes here).
// ---------------------------------------------------------------------------
__device__ __forceinline__ float gelu_exact(float x) {
    return 0.5f * x * (1.0f + erff(x * 0.70710678118654752f));
}

template <int EPI>  // 0: +bias   1: gelu(+bias) with clamp
__global__ __launch_bounds__(256, 2)
void sgemm_k(const float* __restrict__ A, const float* __restrict__ B,
             const float* __restrict__ bias, float* __restrict__ C,
             int M, int N, int K)
{
    __shared__ float As[8][128];
    __shared__ float Bs[8][128];

    const int tid = threadIdx.x;
    const int tx  = tid & 15;        // 0..15 -> N micro
    const int ty  = tid >> 4;        // 0..15 -> M micro
    const int row0 = blockIdx.y * 128;
    const int col0 = blockIdx.x * 128;

    const int arow = tid >> 1;       // 0..127
    const int acol = (tid & 1) * 4;  // 0 or 4
    const int brow = tid >> 5;       // 0..7
    const int bcol = (tid & 31) * 4; // 0..124

    const float* Aptr = A + (size_t)(row0 + arow) * K + acol;
    const float* Bptr = B + (size_t)brow * N + col0 + bcol;

    float acc[8][8];
#pragma unroll
    for (int i = 0; i < 8; i++)
#pragma unroll
        for (int j = 0; j < 8; j++) acc[i][j] = 0.0f;

    for (int k0 = 0; k0 < K; k0 += 8) {
        float4 a = *(const float4*)(Aptr + k0);
        float4 b = *(const float4*)(Bptr + (size_t)k0 * N);
        As[acol + 0][arow] = a.x;
        As[acol + 1][arow] = a.y;
        As[acol + 2][arow] = a.z;
        As[acol + 3][arow] = a.w;
        *(float4*)&Bs[brow][bcol] = b;
        __syncthreads();

#pragma unroll
        for (int kk = 0; kk < 8; kk++) {
            float ra[8], rb[8];
#pragma unroll
            for (int i = 0; i < 8; i++) ra[i] = As[kk][ty * 8 + i];
#pragma unroll
            for (int j = 0; j < 8; j++) rb[j] = Bs[kk][tx * 8 + j];
#pragma unroll
            for (int i = 0; i < 8; i++)
#pragma unroll
                for (int j = 0; j < 8; j++) acc[i][j] = fmaf(ra[i], rb[j], acc[i][j]);
        }
        __syncthreads();
    }

    // epilogue
    float bz[8];
#pragma unroll
    for (int j = 0; j < 8; j++) bz[j] = bias[col0 + tx * 8 + j];

#pragma unroll
    for (int i = 0; i < 8; i++) {
        const int r = row0 + ty * 8 + i;
        float v[8];
#pragma unroll
        for (int j = 0; j < 8; j++) {
            float t = acc[i][j] + bz[j];
            if (EPI == 1) {
                t = gelu_exact(t);
                t = fminf(fmaxf(t, -1e9f), 1e9f);
            }
            v[j] = t;
        }
        float4 o0 = make_float4(v[0], v[1], v[2], v[3]);
        float4 o1 = make_float4(v[4], v[5], v[6], v[7]);
        float* cp = C + (size_t)r * N + col0 + tx * 8;
        *(float4*)(cp + 0) = o0;
        *(float4*)(cp + 4) = o1;
    }
}

// ---------------------------------------------------------------------------
// Flash-style attention, SIMT. One block = 64 queries of one (b,h).
// 256 threads: 16x16 grid, 4x4 micro-tiles for both QK^T and PV.
// K tile stored transposed in smem (KsT[kk][key]) for conflict-free float4.
// ctx = softmax(QK^T/8 clamp)@V + 1e-9 * colsum(V)  (epsilon fold-in).
// ---------------------------------------------------------------------------
#define ATTN_PAD  68           // row stride (keeps 16B alignment + bank spread)
#define ATTN_TILE (64 * ATTN_PAD)
#define ATTN_SMEM ((4 * ATTN_TILE + 3 * 64) * 4)

__global__ __launch_bounds__(256)
void attn_kernel(const float* __restrict__ Q, const float* __restrict__ K,
                 const float* __restrict__ V, float* __restrict__ O)
{
    extern __shared__ float sm[];
    float* Qs   = sm;                       // [q][d]   stride 68
    float* KsT  = sm + ATTN_TILE;           // [d][key] stride 68 (transposed)
    float* Vs   = sm + 2 * ATTN_TILE;       // [key][d] stride 68
    float* Ss   = sm + 3 * ATTN_TILE;       // [q][key] stride 68
    float* m_s  = sm + 4 * ATTN_TILE;
    float* l_s  = m_s + 64;
    float* sc_s = l_s + 64;

    const int tid = threadIdx.x;
    const int tx  = tid & 15;
    const int ty  = tid >> 4;
    const int q0  = ty * 4;

    const int bh = blockIdx.y;
    const int b  = bh >> 4;
    const int h  = bh & 15;
    const int qstart = blockIdx.x * 64;
    const size_t base = (size_t)b * SEQ * H + (size_t)h * HD;

    // load Q tile
#pragma unroll
    for (int it = 0; it < 16; it++) {
        int idx = tid + it * 256;
        int r = idx >> 6, c = idx & 63;
        Qs[r * ATTN_PAD + c] = Q[base + (size_t)(qstart + r) * H + c];
    }
    if (tid < 64) { m_s[tid] = -1e30f; l_s[tid] = 0.0f; }

    float acc[4][4];
#pragma unroll
    for (int i = 0; i < 4; i++)
#pragma unroll
        for (int j = 0; j < 4; j++) acc[i][j] = 0.0f;
    float sv[4] = {0.f, 0.f, 0.f, 0.f};

    __syncthreads();

    for (int kt = 0; kt < SEQ / 64; kt++) {
        const int kstart = kt * 64;
        // load K (transposed) and V tiles
#pragma unroll
        for (int it = 0; it < 16; it++) {
            int idx = tid + it * 256;
            int r = idx >> 6, c = idx & 63;
            size_t gi = base + (size_t)(kstart + r) * H + c;
            KsT[c * ATTN_PAD + r] = K[gi];
            Vs[r * ATTN_PAD + c]  = V[gi];
        }
        __syncthreads();

        // scores: s[i][j] = Q[q0+i,:] . K[tx*4+j,:]
        float s[4][4];
#pragma unroll
        for (int i = 0; i < 4; i++)
#pragma unroll
            for (int j = 0; j < 4; j++) s[i][j] = 0.0f;

#pragma unroll
        for (int kk = 0; kk < 64; kk++) {
            float rq[4];
#pragma unroll
            for (int i = 0; i < 4; i++) rq[i] = Qs[(q0 + i) * ATTN_PAD + kk];
            float4 rk4 = *(const float4*)&KsT[kk * ATTN_PAD + tx * 4];
            float rk[4] = {rk4.x, rk4.y, rk4.z, rk4.w};
#pragma unroll
            for (int i = 0; i < 4; i++)
#pragma unroll
                for (int j = 0; j < 4; j++) s[i][j] = fmaf(rq[i], rk[j], s[i][j]);
        }

        // scale, clamp, stage into Ss
#pragma unroll
        for (int i = 0; i < 4; i++)
#pragma unroll
            for (int j = 0; j < 4; j++) {
                float v = s[i][j] * 0.125f;
                v = fminf(fmaxf(v, -1e9f), 1e9f);
                Ss[(q0 + i) * ATTN_PAD + tx * 4 + j] = v;
            }
        __syncthreads();

        // online softmax per row (threads 0..63)
        if (tid < 64) {
            const int r = tid;
            float mo = m_s[r];
            float mt = mo;
#pragma unroll 8
            for (int j = 0; j < 64; j++) mt = fmaxf(mt, Ss[r * ATTN_PAD + j]);
            float sc = __expf(mo - mt);
            float sum = 0.0f;
#pragma unroll 8
            for (int j = 0; j < 64; j++) {
                float e = __expf(Ss[r * ATTN_PAD + j] - mt);
                Ss[r * ATTN_PAD + j] = e;
                sum += e;
            }
            m_s[r]  = mt;
            l_s[r]  = l_s[r] * sc + sum;
            sc_s[r] = sc;
        }
        __syncthreads();

        // rescale accumulators
        float scl[4];
#pragma unroll
        for (int i = 0; i < 4; i++) scl[i] = sc_s[q0 + i];
#pragma unroll
        for (int i = 0; i < 4; i++)
#pragma unroll
            for (int j = 0; j < 4; j++) acc[i][j] *= scl[i];

        // PV: acc += P @ V; also accumulate colsum(V) for the 1e-9 epsilon
#pragma unroll
        for (int kk = 0; kk < 64; kk++) {
            float rp[4];
#pragma unroll
            for (int i = 0; i < 4; i++) rp[i] = Ss[(q0 + i) * ATTN_PAD + kk];
            float4 rv4 = *(const float4*)&Vs[kk * ATTN_PAD + tx * 4];
            float rv[4] = {rv4.x, rv4.y, rv4.z, rv4.w};
#pragma unroll
            for (int j = 0; j < 4; j++) sv[j] += rv[j];
#pragma unroll
            for (int i = 0; i < 4; i++)
#pragma unroll
                for (int j = 0; j < 4; j++) acc[i][j] = fmaf(rp[i], rv[j], acc[i][j]);
        }
        __syncthreads();
    }

    // epilogue: normalize + epsilon term, write ctx
    float linv[4];
#pragma unroll
    for (int i = 0; i < 4; i++) linv[i] = 1.0f / l_s[q0 + i];
#pragma unroll
    for (int i = 0; i < 4; i++) {
        float4 o;
        o.x = acc[i][0] * linv[i] + 1e-9f * sv[0];
        o.y = acc[i][1] * linv[i] + 1e-9f * sv[1];
        o.z = acc[i][2] * linv[i] + 1e-9f * sv[2];
        o.w = acc[i][3] * linv[i] + 1e-9f * sv[3];
        *(float4*)&O[base + (size_t)(qstart + q0 + i) * H + tx * 4] = o;
    }
}

// ---------------------------------------------------------------------------
// Fused residual-add + LayerNorm over H=1024. One block per row, 256 threads,
// one float4 per thread.
// ---------------------------------------------------------------------------
__global__ __launch_bounds__(256)
void add_ln_kernel(const float* __restrict__ A, const float* __restrict__ Bres,
                   const float* __restrict__ gam, const float* __restrict__ bet,
                   float* __restrict__ out)
{
    const int row = blockIdx.x;
    const int tid = threadIdx.x;
    const float4 va = ((const float4*)(A    + (size_t)row * H))[tid];
    const float4 vb = ((const float4*)(Bres + (size_t)row * H))[tid];
    float x0 = va.x + vb.x, x1 = va.y + vb.y, x2 = va.z + vb.z, x3 = va.w + vb.w;

    __shared__ float red[8];
    __shared__ float s_mu, s_rstd;

    float s = x0 + x1 + x2 + x3;
#pragma unroll
    for (int o = 16; o; o >>= 1) s += __shfl_down_sync(0xffffffffu, s, o);
    if ((tid & 31) == 0) red[tid >> 5] = s;
    __syncthreads();
    if (tid == 0) {
        float t = 0.f;
#pragma unroll
        for (int i = 0; i < 8; i++) t += red[i];
        s_mu = t * (1.0f / H);
    }
    __syncthreads();
    const float mu = s_mu;
    float d0 = x0 - mu, d1 = x1 - mu, d2 = x2 - mu, d3 = x3 - mu;
    float ss = d0 * d0 + d1 * d1 + d2 * d2 + d3 * d3;
#pragma unroll
    for (int o = 16; o; o >>= 1) ss += __shfl_down_sync(0xffffffffu, ss, o);
    __syncthreads();               // red reuse safety
    if ((tid & 31) == 0) red[tid >> 5] = ss;
    __syncthreads();
    if (tid == 0) {
        float t = 0.f;
#pragma unroll
        for (int i = 0; i < 8; i++) t += red[i];
        s_rstd = rsqrtf(t * (1.0f / H) + 1e-12f);
    }
    __syncthreads();
    const float rstd = s_rstd;

    const float4 g4 = ((const float4*)gam)[tid];
    const float4 b4 = ((const float4*)bet)[tid];
    float4 o;
    o.x = d0 * rstd * g4.x + b4.x;
    o.y = d1 * rstd * g4.y + b4.y;
    o.z = d2 * rstd * g4.z + b4.z;
    o.w = d3 * rstd * g4.w + b4.w;
    ((float4*)(out + (size_t)row * H))[tid] = o;
}

// ---------------------------------------------------------------------------
// Launch
// ---------------------------------------------------------------------------
extern "C" void kernel_launch(void* const* d_in, const int* in_sizes, int n_in,
                              void* d_out, int out_size)
{
    const float* hs   = (const float*)d_in[0];
    const float* Wq   = (const float*)d_in[1];
    const float* bq   = (const float*)d_in[2];
    const float* Wk   = (const float*)d_in[3];
    const float* bk   = (const float*)d_in[4];
    const float* Wv   = (const float*)d_in[5];
    const float* bv   = (const float*)d_in[6];
    const float* ln1g = (const float*)d_in[7];
    const float* ln1b = (const float*)d_in[8];
    const float* W1   = (const float*)d_in[9];
    const float* b1   = (const float*)d_in[10];
    const float* W2   = (const float*)d_in[11];
    const float* b2   = (const float*)d_in[12];
    const float* ln2g = (const float*)d_in[13];
    const float* ln2b = (const float*)d_in[14];
    float* out = (float*)d_out;

    static float *pq = nullptr, *pk = nullptr, *pv = nullptr, *pctx = nullptr,
                 *px = nullptr, *pinter = nullptr, *pffn = nullptr;
    if (!pq) {  // first call is the (uncaptured) correctness run
        cudaGetSymbolAddress((void**)&pq,     g_q);
        cudaGetSymbolAddress((void**)&pk,     g_k);
        cudaGetSymbolAddress((void**)&pv,     g_v);
        cudaGetSymbolAddress((void**)&pctx,   g_ctx);
        cudaGetSymbolAddress((void**)&px,     g_x);
        cudaGetSymbolAddress((void**)&pinter, g_inter);
        cudaGetSymbolAddress((void**)&pffn,   g_ffn);
        cudaFuncSetAttribute(attn_kernel,
                             cudaFuncAttributeMaxDynamicSharedMemorySize,
                             ATTN_SMEM);
    }

    const dim3 blk(256);
    // QKV projections
    sgemm_k<0><<<dim3(H / 128, BTOK / 128), blk>>>(hs, Wq, bq, pq, BTOK, H, H);
    sgemm_k<0><<<dim3(H / 128, BTOK / 128), blk>>>(hs, Wk, bk, pk, BTOK, H, H);
    sgemm_k<0><<<dim3(H / 128, BTOK / 128), blk>>>(hs, Wv, bv, pv, BTOK, H, H);
    // attention -> ctx
    attn_kernel<<<dim3(SEQ / 64, 4 * NH), 256, ATTN_SMEM>>>(pq, pk, pv, pctx);
    // residual + LN1 -> x
    add_ln_kernel<<<BTOK, 256>>>(hs, pctx, ln1g, ln1b, px);
    // FFN
    sgemm_k<1><<<dim3(FF / 128, BTOK / 128), blk>>>(px, W1, b1, pinter, BTOK, FF, H);
    sgemm_k<0><<<dim3(H / 128, BTOK / 128), blk>>>(pinter, W2, b2, pffn, BTOK, H, FF);
    // residual + LN2 -> out
    add_ln_kernel<<<BTOK, 256>>>(pffn, px, ln2g, ln2b, out);
}

// round 4
// speedup vs baseline: 1.0563x; 1.0563x over previous
#include <cuda_runtime.h>
#include <math.h>

#define H    1024
#define NH   16
#define HD   64
#define FF   4096
#define SEQ  2048
#define BTOK 8192   // 4 * 2048 tokens

// ---------------------------------------------------------------------------
// Scratch (static __device__ globals: allocation-free rule)
// ---------------------------------------------------------------------------
__device__ float g_q[BTOK * H];
__device__ float g_k[BTOK * H];
__device__ float g_v[BTOK * H];
__device__ float g_ctx[BTOK * H];
__device__ float g_x[BTOK * H];
__device__ float g_inter[(size_t)BTOK * FF];
__device__ float g_ffn[BTOK * H];

// ---------------------------------------------------------------------------
// Generic SGEMM: C[M,N] = A[M,K] @ B[K,N] + bias, optional exact-gelu+clamp.
// 128x128 block tile, BK=8, 256 threads, 8x8 register micro-tile.
// Assumes M%128==0, N%128==0, K%8==0 (true for all shapes here).
// ---------------------------------------------------------------------------
__device__ __forceinline__ float gelu_exact(float x) {
    return 0.5f * x * (1.0f + erff(x * 0.70710678118654752f));
}

template <int EPI>  // 0: +bias   1: gelu(+bias) with clamp
__global__ __launch_bounds__(256, 2)
void sgemm_k(const float* __restrict__ A, const float* __restrict__ B,
             const float* __restrict__ bias, float* __restrict__ C,
             int M, int N, int K)
{
    __shared__ float As[8][128];
    __shared__ float Bs[8][128];

    const int tid = threadIdx.x;
    const int tx  = tid & 15;        // 0..15 -> N micro
    const int ty  = tid >> 4;        // 0..15 -> M micro
    const int row0 = blockIdx.y * 128;
    const int col0 = blockIdx.x * 128;

    const int arow = tid >> 1;       // 0..127
    const int acol = (tid & 1) * 4;  // 0 or 4
    const int brow = tid >> 5;       // 0..7
    const int bcol = (tid & 31) * 4; // 0..124

    const float* Aptr = A + (size_t)(row0 + arow) * K + acol;
    const float* Bptr = B + (size_t)brow * N + col0 + bcol;

    float acc[8][8];
#pragma unroll
    for (int i = 0; i < 8; i++)
#pragma unroll
        for (int j = 0; j < 8; j++) acc[i][j] = 0.0f;

    for (int k0 = 0; k0 < K; k0 += 8) {
        float4 a = *(const float4*)(Aptr + k0);
        float4 b = *(const float4*)(Bptr + (size_t)k0 * N);
        As[acol + 0][arow] = a.x;
        As[acol + 1][arow] = a.y;
        As[acol + 2][arow] = a.z;
        As[acol + 3][arow] = a.w;
        *(float4*)&Bs[brow][bcol] = b;
        __syncthreads();

#pragma unroll
        for (int kk = 0; kk < 8; kk++) {
            float ra[8], rb[8];
#pragma unroll
            for (int i = 0; i < 8; i++) ra[i] = As[kk][ty * 8 + i];
#pragma unroll
            for (int j = 0; j < 8; j++) rb[j] = Bs[kk][tx * 8 + j];
#pragma unroll
            for (int i = 0; i < 8; i++)
#pragma unroll
                for (int j = 0; j < 8; j++) acc[i][j] = fmaf(ra[i], rb[j], acc[i][j]);
        }
        __syncthreads();
    }

    // epilogue
    float bz[8];
#pragma unroll
    for (int j = 0; j < 8; j++) bz[j] = bias[col0 + tx * 8 + j];

#pragma unroll
    for (int i = 0; i < 8; i++) {
        const int r = row0 + ty * 8 + i;
        float v[8];
#pragma unroll
        for (int j = 0; j < 8; j++) {
            float t = acc[i][j] + bz[j];
            if (EPI == 1) {
                t = gelu_exact(t);
                t = fminf(fmaxf(t, -1e9f), 1e9f);
            }
            v[j] = t;
        }
        float4 o0 = make_float4(v[0], v[1], v[2], v[3]);
        float4 o1 = make_float4(v[4], v[5], v[6], v[7]);
        float* cp = C + (size_t)r * N + col0 + tx * 8;
        *(float4*)(cp + 0) = o0;
        *(float4*)(cp + 4) = o1;
    }
}

// ---------------------------------------------------------------------------
// Flash-style attention, SIMT. One block = 64 queries of one (b,h).
// 256 threads: 16x16 grid, 4x4 micro-tiles for both QK^T and PV.
// K tile stored transposed in smem (KsT[kk][key]) for conflict-free float4.
// ctx = softmax(QK^T/8 clamp)@V + 1e-9 * colsum(V)  (epsilon fold-in).
// ---------------------------------------------------------------------------
#define ATTN_PAD  68           // row stride (keeps 16B alignment + bank spread)
#define ATTN_TILE (64 * ATTN_PAD)
#define ATTN_SMEM ((4 * ATTN_TILE + 3 * 64) * 4)

__global__ __launch_bounds__(256)
void attn_kernel(const float* __restrict__ Q, const float* __restrict__ K,
                 const float* __restrict__ V, float* __restrict__ O)
{
    extern __shared__ float sm[];
    float* Qs   = sm;                       // [q][d]   stride 68
    float* KsT  = sm + ATTN_TILE;           // [d][key] stride 68 (transposed)
    float* Vs   = sm + 2 * ATTN_TILE;       // [key][d] stride 68
    float* Ss   = sm + 3 * ATTN_TILE;       // [q][key] stride 68
    float* m_s  = sm + 4 * ATTN_TILE;
    float* l_s  = m_s + 64;
    float* sc_s = l_s + 64;

    const int tid = threadIdx.x;
    const int tx  = tid & 15;
    const int ty  = tid >> 4;
    const int q0  = ty * 4;

    const int bh = blockIdx.y;
    const int b  = bh >> 4;
    const int h  = bh & 15;
    const int qstart = blockIdx.x * 64;
    const size_t base = (size_t)b * SEQ * H + (size_t)h * HD;

    // load Q tile
#pragma unroll
    for (int it = 0; it < 16; it++) {
        int idx = tid + it * 256;
        int r = idx >> 6, c = idx & 63;
        Qs[r * ATTN_PAD + c] = Q[base + (size_t)(qstart + r) * H + c];
    }
    if (tid < 64) { m_s[tid] = -1e30f; l_s[tid] = 0.0f; }

    float acc[4][4];
#pragma unroll
    for (int i = 0; i < 4; i++)
#pragma unroll
        for (int j = 0; j < 4; j++) acc[i][j] = 0.0f;
    float sv[4] = {0.f, 0.f, 0.f, 0.f};

    __syncthreads();

    for (int kt = 0; kt < SEQ / 64; kt++) {
        const int kstart = kt * 64;
        // load K (transposed) and V tiles
#pragma unroll
        for (int it = 0; it < 16; it++) {
            int idx = tid + it * 256;
            int r = idx >> 6, c = idx & 63;
            size_t gi = base + (size_t)(kstart + r) * H + c;
            KsT[c * ATTN_PAD + r] = K[gi];
            Vs[r * ATTN_PAD + c]  = V[gi];
        }
        __syncthreads();

        // scores: s[i][j] = Q[q0+i,:] . K[tx*4+j,:]
        float s[4][4];
#pragma unroll
        for (int i = 0; i < 4; i++)
#pragma unroll
            for (int j = 0; j < 4; j++) s[i][j] = 0.0f;

#pragma unroll
        for (int kk = 0; kk < 64; kk++) {
            float rq[4];
#pragma unroll
            for (int i = 0; i < 4; i++) rq[i] = Qs[(q0 + i) * ATTN_PAD + kk];
            float4 rk4 = *(const float4*)&KsT[kk * ATTN_PAD + tx * 4];
            float rk[4] = {rk4.x, rk4.y, rk4.z, rk4.w};
#pragma unroll
            for (int i = 0; i < 4; i++)
#pragma unroll
                for (int j = 0; j < 4; j++) s[i][j] = fmaf(rq[i], rk[j], s[i][j]);
        }

        // scale, clamp, stage into Ss
#pragma unroll
        for (int i = 0; i < 4; i++)
#pragma unroll
            for (int j = 0; j < 4; j++) {
                float v = s[i][j] * 0.125f;
                v = fminf(fmaxf(v, -1e9f), 1e9f);
                Ss[(q0 + i) * ATTN_PAD + tx * 4 + j] = v;
            }
        __syncthreads();

        // online softmax per row (threads 0..63)
        if (tid < 64) {
            const int r = tid;
            float mo = m_s[r];
            float mt = mo;
#pragma unroll 8
            for (int j = 0; j < 64; j++) mt = fmaxf(mt, Ss[r * ATTN_PAD + j]);
            float sc = __expf(mo - mt);
            float sum = 0.0f;
#pragma unroll 8
            for (int j = 0; j < 64; j++) {
                float e = __expf(Ss[r * ATTN_PAD + j] - mt);
                Ss[r * ATTN_PAD + j] = e;
                sum += e;
            }
            m_s[r]  = mt;
            l_s[r]  = l_s[r] * sc + sum;
            sc_s[r] = sc;
        }
        __syncthreads();

        // rescale accumulators
        float scl[4];
#pragma unroll
        for (int i = 0; i < 4; i++) scl[i] = sc_s[q0 + i];
#pragma unroll
        for (int i = 0; i < 4; i++)
#pragma unroll
            for (int j = 0; j < 4; j++) acc[i][j] *= scl[i];

        // PV: acc += P @ V; also accumulate colsum(V) for the 1e-9 epsilon
#pragma unroll
        for (int kk = 0; kk < 64; kk++) {
            float rp[4];
#pragma unroll
            for (int i = 0; i < 4; i++) rp[i] = Ss[(q0 + i) * ATTN_PAD + kk];
            float4 rv4 = *(const float4*)&Vs[kk * ATTN_PAD + tx * 4];
            float rv[4] = {rv4.x, rv4.y, rv4.z, rv4.w};
#pragma unroll
            for (int j = 0; j < 4; j++) sv[j] += rv[j];
#pragma unroll
            for (int i = 0; i < 4; i++)
#pragma unroll
                for (int j = 0; j < 4; j++) acc[i][j] = fmaf(rp[i], rv[j], acc[i][j]);
        }
        __syncthreads();
    }

    // epilogue: normalize + epsilon term, write ctx
    float linv[4];
#pragma unroll
    for (int i = 0; i < 4; i++) linv[i] = 1.0f / l_s[q0 + i];
#pragma unroll
    for (int i = 0; i < 4; i++) {
        float4 o;
        o.x = acc[i][0] * linv[i] + 1e-9f * sv[0];
        o.y = acc[i][1] * linv[i] + 1e-9f * sv[1];
        o.z = acc[i][2] * linv[i] + 1e-9f * sv[2];
        o.w = acc[i][3] * linv[i] + 1e-9f * sv[3];
        *(float4*)&O[base + (size_t)(qstart + q0 + i) * H + tx * 4] = o;
    }
}

// ---------------------------------------------------------------------------
// Fused residual-add + LayerNorm over H=1024. One block per row, 256 threads,
// one float4 per thread.
// ---------------------------------------------------------------------------
__global__ __launch_bounds__(256)
void add_ln_kernel(const float* __restrict__ A, const float* __restrict__ Bres,
                   const float* __restrict__ gam, const float* __restrict__ bet,
                   float* __restrict__ out)
{
    const int row = blockIdx.x;
    const int tid = threadIdx.x;
    const float4 va = ((const float4*)(A    + (size_t)row * H))[tid];
    const float4 vb = ((const float4*)(Bres + (size_t)row * H))[tid];
    float x0 = va.x + vb.x, x1 = va.y + vb.y, x2 = va.z + vb.z, x3 = va.w + vb.w;

    __shared__ float red[8];
    __shared__ float s_mu, s_rstd;

    float s = x0 + x1 + x2 + x3;
#pragma unroll
    for (int o = 16; o; o >>= 1) s += __shfl_down_sync(0xffffffffu, s, o);
    if ((tid & 31) == 0) red[tid >> 5] = s;
    __syncthreads();
    if (tid == 0) {
        float t = 0.f;
#pragma unroll
        for (int i = 0; i < 8; i++) t += red[i];
        s_mu = t * (1.0f / H);
    }
    __syncthreads();
    const float mu = s_mu;
    float d0 = x0 - mu, d1 = x1 - mu, d2 = x2 - mu, d3 = x3 - mu;
    float ss = d0 * d0 + d1 * d1 + d2 * d2 + d3 * d3;
#pragma unroll
    for (int o = 16; o; o >>= 1) ss += __shfl_down_sync(0xffffffffu, ss, o);
    __syncthreads();               // red reuse safety
    if ((tid & 31) == 0) red[tid >> 5] = ss;
    __syncthreads();
    if (tid == 0) {
        float t = 0.f;
#pragma unroll
        for (int i = 0; i < 8; i++) t += red[i];
        s_rstd = rsqrtf(t * (1.0f / H) + 1e-12f);
    }
    __syncthreads();
    const float rstd = s_rstd;

    const float4 g4 = ((const float4*)gam)[tid];
    const float4 b4 = ((const float4*)bet)[tid];
    float4 o;
    o.x = d0 * rstd * g4.x + b4.x;
    o.y = d1 * rstd * g4.y + b4.y;
    o.z = d2 * rstd * g4.z + b4.z;
    o.w = d3 * rstd * g4.w + b4.w;
    ((float4*)(out + (size_t)row * H))[tid] = o;
}

// ---------------------------------------------------------------------------
// Launch
// ---------------------------------------------------------------------------
extern "C" void kernel_launch(void* const* d_in, const int* in_sizes, int n_in,
                              void* d_out, int out_size)
{
    const float* hs   = (const float*)d_in[0];
    const float* Wq   = (const float*)d_in[1];
    const float* bq   = (const float*)d_in[2];
    const float* Wk   = (const float*)d_in[3];
    const float* bk   = (const float*)d_in[4];
    const float* Wv   = (const float*)d_in[5];
    const float* bv   = (const float*)d_in[6];
    const float* ln1g = (const float*)d_in[7];
    const float* ln1b = (const float*)d_in[8];
    const float* W1   = (const float*)d_in[9];
    const float* b1   = (const float*)d_in[10];
    const float* W2   = (const float*)d_in[11];
    const float* b2   = (const float*)d_in[12];
    const float* ln2g = (const float*)d_in[13];
    const float* ln2b = (const float*)d_in[14];
    float* out = (float*)d_out;

    static float *pq = nullptr, *pk = nullptr, *pv = nullptr, *pctx = nullptr,
                 *px = nullptr, *pinter = nullptr, *pffn = nullptr;
    if (!pq) {  // first call is the (uncaptured) correctness run
        cudaGetSymbolAddress((void**)&pq,     g_q);
        cudaGetSymbolAddress((void**)&pk,     g_k);
        cudaGetSymbolAddress((void**)&pv,     g_v);
        cudaGetSymbolAddress((void**)&pctx,   g_ctx);
        cudaGetSymbolAddress((void**)&px,     g_x);
        cudaGetSymbolAddress((void**)&pinter, g_inter);
        cudaGetSymbolAddress((void**)&pffn,   g_ffn);
        cudaFuncSetAttribute(attn_kernel,
                             cudaFuncAttributeMaxDynamicSharedMemorySize,
                             ATTN_SMEM);
    }

    const dim3 blk(256);
    // QKV projections
    sgemm_k<0><<<dim3(H / 128, BTOK / 128), blk>>>(hs, Wq, bq, pq, BTOK, H, H);
    sgemm_k<0><<<dim3(H / 128, BTOK / 128), blk>>>(hs, Wk, bk, pk, BTOK, H, H);
    sgemm_k<0><<<dim3(H / 128, BTOK / 128), blk>>>(hs, Wv, bv, pv, BTOK, H, H);
    // attention -> ctx
    attn_kernel<<<dim3(SEQ / 64, 4 * NH), 256, ATTN_SMEM>>>(pq, pk, pv, pctx);
    // residual + LN1 -> x
    add_ln_kernel<<<BTOK, 256>>>(hs, pctx, ln1g, ln1b, px);
    // FFN
    sgemm_k<1><<<dim3(FF / 128, BTOK / 128), blk>>>(px, W1, b1, pinter, BTOK, FF, H);
    sgemm_k<0><<<dim3(H / 128, BTOK / 128), blk>>>(pinter, W2, b2, pffn, BTOK, H, FF);
    // residual + LN2 -> out
    add_ln_kernel<<<BTOK, 256>>>(pffn, px, ln2g, ln2b, out);
}